// round 9
// baseline (speedup 1.0000x reference)
#include <cuda_runtime.h>
#include <math.h>

#define NUM_CLASSES 10
#define Hh 480
#define Ww 640
#define SKIP 8
#define GY 60
#define GX 80
#define P  4800
#define NMAX 8
#define EPSF 1e-6f
#define INLIER 0.9f
#define VTILE 512
#define CBLK  128                        // candidates per vote block (1 per thread-lane)
#define NSLICE 4
#define VTHREADS (CBLK * NSLICE)         // 512
#define VOTE_BX ((P + CBLK - 1) / CBLK)  // 38
#define KD (NUM_CLASSES - 1)

// ---------------- device scratch ----------------
static __device__ int      g_sidx[NMAX][P];       // sorted pos -> pixel index
static __device__ int      g_sklass[NMAX][P];     // sorted pos -> class
static __device__ float4   g_sxyuv[NMAX][P];      // sorted (x,y,u,v)
static __device__ float    g_sd[NMAX][P];         // sorted d
static __device__ int      g_segStart[NMAX][11];
static __device__ float    g_counts[NMAX][10];
static __device__ unsigned g_bestkey[NMAX][10];   // (cnt<<13)|(8191-c)
static __device__ unsigned g_done[NMAX];

// shared inlier predicate: fast quadratic test + exact IEEE fallback in guard band.
// Used identically by vote and epilogue so inlier sets match exactly.
__device__ __forceinline__ bool hv_inlier(float fcx, float fcy, float4 t)
{
    float dx   = fcx - t.x;
    float dy   = fcy - t.y;
    float s    = fmaf(dx, dx, dy * dy);
    float dot  = fmaf(t.z, dx, t.w * dy);
    float dotp = fmaxf(dot, 0.0f);
    float gd   = fmaf(dotp, dotp, -0.81f * s);
    if (fabsf(gd) < 1e-5f * s) {
        float rd = sqrtf(s) + EPSF;              // exact reference formula
        return (dot / rd) > INLIER;
    }
    return gd > 0.0f;
}

// ================= kernel A: labels-only counting sort (1 block/n) =================
__global__ void __launch_bounds__(1024, 1)
hv_sort_kernel(const int* __restrict__ label)
{
    const int n    = blockIdx.x;
    const int tid  = threadIdx.x;
    const int warp = tid >> 5;
    const int lane = tid & 31;
    const unsigned FULL = 0xffffffffu;

    __shared__ int s_lab[P];
    __shared__ int s_cnt[32][10];
    __shared__ int s_off[32][10];

    if (tid < 10) g_bestkey[n][tid] = 0u;
    if (tid == 10) g_done[n] = 0u;

    const int* lab2d = label + (size_t)n * Hh * Ww;
    for (int p = tid; p < P; p += 1024) {
        int iy = p / GX, ix = p - iy * GX;
        s_lab[p] = lab2d[iy * SKIP * Ww + ix * SKIP];
    }
    __syncthreads();

    // per-chunk per-class counts (warp = chunk of 150 pixels)
    int cnt[10];
    #pragma unroll
    for (int k = 0; k < 10; k++) cnt[k] = 0;
    const int cbase = warp * 150;
    #pragma unroll
    for (int s = 0; s < 5; s++) {
        int o = s * 32 + lane;
        int l = (o < 150) ? s_lab[cbase + o] : -1;
        #pragma unroll
        for (int k = 0; k < 10; k++) {
            unsigned m = __ballot_sync(FULL, l == k);
            cnt[k] += __popc(m);
        }
    }
    if (lane == 0) {
        #pragma unroll
        for (int k = 0; k < 10; k++) s_cnt[warp][k] = cnt[k];
    }
    __syncthreads();

    // warp 0: shfl-scan chunk offsets + segment starts
    if (warp == 0) {
        int segrun = 0;
        if (lane == 0) g_segStart[n][0] = 0;
        #pragma unroll
        for (int k = 0; k < 10; k++) {
            int v = s_cnt[lane][k];
            int incl = v;
            #pragma unroll
            for (int d = 1; d < 32; d <<= 1) {
                int t = __shfl_up_sync(FULL, incl, d);
                if (lane >= d) incl += t;
            }
            int excl  = incl - v;
            int total = __shfl_sync(FULL, incl, 31);
            if (k >= 1) {
                s_off[lane][k] = segrun + excl;
                if (lane == 0) g_segStart[n][k] = segrun;
                segrun += total;
            }
            if (lane == 0) g_counts[n][k] = (float)total;
        }
        if (lane == 0) g_segStart[n][10] = segrun;
    }
    __syncthreads();

    // parallel stable scatter of indices (warp = chunk)
    int off[10];
    #pragma unroll
    for (int k = 1; k < 10; k++) off[k] = s_off[warp][k];
    #pragma unroll
    for (int s = 0; s < 5; s++) {
        int o = s * 32 + lane;
        int j = cbase + o;
        int l = (o < 150) ? s_lab[j] : -1;
        #pragma unroll
        for (int k = 1; k < 10; k++) {
            unsigned m = __ballot_sync(FULL, l == k);
            if (l == k) {
                int pos = off[k] + __popc(m & ((1u << lane) - 1u));
                g_sidx[n][pos]   = j;
                g_sklass[n][pos] = k;
            }
            off[k] += __popc(m);
        }
    }
}

// ================= kernel B: parallel gather/compute + zero train outputs =================
__global__ void hv_gather_kernel(const float* __restrict__ vp,
                                 float* __restrict__ out, int N)
{
    const int n   = blockIdx.y;
    const int idx = blockIdx.x * blockDim.x + threadIdx.x;

    // zero train-only slices for this n
    if (idx < KD * 40) {
        out[(size_t)N * KD * 14 + (size_t)n * KD * 40 + idx] = 0.0f;
        out[(size_t)N * KD * 54 + (size_t)n * KD * 40 + idx] = 0.0f;
    }

    if (idx >= g_segStart[n][10]) return;

    int p = g_sidx[n][idx];
    int l = g_sklass[n][idx];
    int iy = p / GX, ix = p - iy * GX;

    const float* v3 = vp + (size_t)n * Hh * Ww * (3 * NUM_CLASSES)
                         + (size_t)(iy * SKIP * Ww + ix * SKIP) * (3 * NUM_CLASSES) + 3 * l;
    float u = v3[0], v = v3[1], w = v3[2];
    float nrm = sqrtf(u * u + v * v) + EPSF;

    g_sxyuv[n][idx] = make_float4((float)(ix * SKIP), (float)(iy * SKIP), u / nrm, v / nrm);
    g_sd[n][idx]    = expf(fminf(fmaxf(w, -3.0f), 3.0f));
}

// ================= kernel C: voting + argmax + last-block epilogue (512 thr) =================
__global__ void __launch_bounds__(VTHREADS)
hv_vote_kernel(const float* __restrict__ extents,
               const float* __restrict__ meta,
               float* __restrict__ out, int N)
{
    const int n = blockIdx.z;
    const int k = blockIdx.y + 1;
    const int tid   = threadIdx.x;
    const int cl    = tid & (CBLK - 1);          // candidate lane 0..127
    const int slice = tid >> 7;                  // 0..3
    const int c     = blockIdx.x * CBLK + cl;
    const unsigned FULL = 0xffffffffu;

    __shared__ float4   sxy[VTILE];
    __shared__ int      s_pcnt[NSLICE][CBLK];
    __shared__ unsigned skey[CBLK];
    __shared__ int      s_last;

    const int beg = g_segStart[n][k];
    const int end = g_segStart[n][k + 1];

    float fcx = 0.f, fcy = 0.f;
    const bool cv = (c < P);
    if (cv) {
        int iy = c / GX, ix = c - iy * GX;
        fcx = (float)(ix * SKIP);
        fcy = (float)(iy * SKIP);
    }

    int cnt = 0;

    for (int base = beg; base < end; base += VTILE) {
        int m = end - base;
        if (m > VTILE) m = VTILE;
        for (int j = tid; j < m; j += VTHREADS)
            sxy[j] = g_sxyuv[n][base + j];
        __syncthreads();
        for (int j = slice; j < m; j += NSLICE) {
            if (hv_inlier(fcx, fcy, sxy[j])) cnt++;
        }
        __syncthreads();
    }

    s_pcnt[slice][cl] = cnt;
    __syncthreads();

    if (slice == 0) {
        int tc = s_pcnt[0][cl] + s_pcnt[1][cl] + s_pcnt[2][cl] + s_pcnt[3][cl];
        skey[cl] = cv ? ((((unsigned)tc) << 13) | (unsigned)(8191 - c)) : 0u;
    }
    __syncthreads();

    for (int s = CBLK / 2; s > 0; s >>= 1) {
        if (tid < s) {
            unsigned o = skey[tid + s];
            if (o > skey[tid]) skey[tid] = o;
        }
        __syncthreads();
    }
    if (tid == 0) {
        atomicMax(&g_bestkey[n][k], skey[0]);
        __threadfence();
        unsigned t = atomicAdd(&g_done[n], 1u);
        s_last = (t == (unsigned)(VOTE_BX * KD - 1)) ? 1 : 0;
    }
    __syncthreads();

    if (!s_last) return;
    __threadfence();

    // ---- last block of this n: winner dsum (1 class per warp, 16 warps) ----
    const int warp = tid >> 5;
    const int lane = tid & 31;
    if (warp >= KD) return;

    const int kk = warp + 1;
    unsigned bkey = g_bestkey[n][kk];
    float votes = (float)(bkey >> 13);
    int   best  = 8191 - (int)(bkey & 8191u);
    int biy = best / GX, bix = best - biy * GX;
    float cx = (float)(bix * SKIP);
    float cy = (float)(biy * SKIP);

    const int kb = g_segStart[n][kk];
    const int ke = g_segStart[n][kk + 1];
    float ds = 0.0f;
    for (int j = kb + lane; j < ke; j += 32) {
        float4 t = g_sxyuv[n][j];
        if (hv_inlier(cx, cy, t)) ds += g_sd[n][j];
    }
    #pragma unroll
    for (int d = 16; d > 0; d >>= 1)
        ds += __shfl_down_sync(FULL, ds, d);

    if (lane == 0) {
        float davg = ds / fmaxf(votes, 1.0f);
        float cntk = g_counts[n][kk];

        bool valid = (votes > 20.0f) && (votes > 0.1f * cntk)
                     && (cntk * (float)(SKIP * SKIP) > 500.0f);

        const float* mt = meta + (size_t)n * 9;
        float fx = mt[0], fy = mt[4], ppx = mt[2], ppy = mt[5];

        float e0 = extents[kk * 3 + 0];
        float e1 = extents[kk * 3 + 1];
        float e2 = extents[kk * 3 + 2];
        float diam = sqrtf(e0 * e0 + e1 * e1 + e2 * e2) + EPSF;

        float hx = 0.5f * diam * fx / fmaxf(davg, EPSF);
        float hy = 0.5f * diam * fy / fmaxf(davg, EPSF);
        float score = valid ? votes : 0.0f;

        float* b = out + ((size_t)n * KD + (kk - 1)) * 7;
        b[0] = (float)n;
        b[1] = (float)kk;
        b[2] = cx - hx;
        b[3] = cy - hy;
        b[4] = cx + hx;
        b[5] = cy + hy;
        b[6] = score;

        float* ps = out + (size_t)N * KD * 7 + ((size_t)n * KD + (kk - 1)) * 7;
        ps[0] = 1.0f; ps[1] = 0.0f; ps[2] = 0.0f; ps[3] = 0.0f;
        ps[4] = (cx - ppx) * davg / fx;
        ps[5] = (cy - ppy) * davg / fy;
        ps[6] = davg;

        out[(size_t)N * KD * 94 + (size_t)n * KD + (kk - 1)] = (float)n;
    }
}

// ---------------- launch ----------------
extern "C" void kernel_launch(void* const* d_in, const int* in_sizes, int n_in,
                              void* d_out, int out_size)
{
    const int*   label   = (const int*)d_in[0];
    const float* vp      = (const float*)d_in[1];
    const float* extents = (const float*)d_in[2];
    const float* meta    = (const float*)d_in[4];
    float* out = (float*)d_out;

    int N = in_sizes[4] / 9;
    if (N < 1) N = 1;
    if (N > NMAX) N = NMAX;

    hv_sort_kernel<<<N, 1024>>>(label);

    dim3 gb((P + 255) / 256, N);
    hv_gather_kernel<<<gb, 256>>>(vp, out, N);

    dim3 gv(VOTE_BX, KD, N);
    hv_vote_kernel<<<gv, VTHREADS>>>(extents, meta, out, N);
}

// round 10
// speedup vs baseline: 1.0468x; 1.0468x over previous
#include <cuda_runtime.h>
#include <math.h>

#define NUM_CLASSES 10
#define Hh 480
#define Ww 640
#define SKIP 8
#define GY 60
#define GX 80
#define P  4800
#define NMAX 8
#define EPSF 1e-6f
#define INLIER 0.9f
#define VTILE 512
#define CBLK  128                        // candidates per vote block
#define NSLICE 4
#define VTHREADS (CBLK * NSLICE)         // 512
#define VOTE_BX ((P + CBLK - 1) / CBLK)  // 38
#define KD (NUM_CLASSES - 1)
#define NCHUNK (P / 32)                  // 150 warp-chunks
#define PBLK 256
#define PGRID ((P + PBLK - 1) / PBLK)    // 19

// ---------------- device scratch ----------------
static __device__ float4   g_pxyuv[NMAX][P];          // natural order (x,y,u,v)
static __device__ float    g_pd[NMAX][P];             // natural order d
static __device__ int      g_plab[NMAX][P];           // natural order label
static __device__ int      g_chunkhist[NMAX][NCHUNK][10];
static __device__ int      g_chunkoff[NMAX][NCHUNK][10];  // exclusive prefix within class
static __device__ float4   g_sxyuv[NMAX][P];          // class-sorted (x,y,u,v)
static __device__ float    g_sd[NMAX][P];             // class-sorted d
static __device__ int      g_segStart[NMAX][11];
static __device__ float    g_counts[NMAX][10];
static __device__ unsigned g_bestkey[NMAX][10];       // (cnt<<13)|(8191-c)

// shared inlier predicate: fast quadratic test + exact IEEE fallback in guard band.
__device__ __forceinline__ bool hv_inlier(float fcx, float fcy, float4 t)
{
    float dx   = fcx - t.x;
    float dy   = fcy - t.y;
    float s    = fmaf(dx, dx, dy * dy);
    float dot  = fmaf(t.z, dx, t.w * dy);
    float dotp = fmaxf(dot, 0.0f);
    float gd   = fmaf(dotp, dotp, -0.81f * s);
    if (fabsf(gd) < 1e-5f * s) {
        float rd = sqrtf(s) + EPSF;              // exact reference formula
        return (dot / rd) > INLIER;
    }
    return gd > 0.0f;
}

// ================= K1: parallel prep + per-chunk hist + output zeroing =================
__global__ void __launch_bounds__(PBLK)
hv_prep_kernel(const int* __restrict__ label,
               const float* __restrict__ vp,
               float* __restrict__ out, int N)
{
    const int n   = blockIdx.y;
    const int idx = blockIdx.x * PBLK + threadIdx.x;
    const int lane = threadIdx.x & 31;
    const unsigned FULL = 0xffffffffu;

    if (blockIdx.x == 0 && threadIdx.x < 10)
        g_bestkey[n][threadIdx.x] = 0u;
    if (idx < KD * 40) {
        out[(size_t)N * KD * 14 + (size_t)n * KD * 40 + idx] = 0.0f;
        out[(size_t)N * KD * 54 + (size_t)n * KD * 40 + idx] = 0.0f;
    }

    int l = -1;
    if (idx < P) {
        int iy = idx / GX, ix = idx - iy * GX;
        l = label[(size_t)n * Hh * Ww + iy * SKIP * Ww + ix * SKIP];
        g_plab[n][idx] = l;

        const float* v3 = vp + (size_t)n * Hh * Ww * (3 * NUM_CLASSES)
                             + (size_t)(iy * SKIP * Ww + ix * SKIP) * (3 * NUM_CLASSES) + 3 * l;
        float u = v3[0], v = v3[1], w = v3[2];
        float nrm = sqrtf(u * u + v * v) + EPSF;
        g_pxyuv[n][idx] = make_float4((float)(ix * SKIP), (float)(iy * SKIP), u / nrm, v / nrm);
        g_pd[n][idx]    = expf(fminf(fmaxf(w, -3.0f), 3.0f));
    }

    // per-warp (32-pixel chunk) class histogram
    int chunk = idx >> 5;
    if (chunk < NCHUNK) {
        #pragma unroll
        for (int k = 0; k < 10; k++) {
            unsigned m = __ballot_sync(FULL, l == k);
            if (lane == 0) g_chunkhist[n][chunk][k] = __popc(m);
        }
    }
}

// ================= K2: chunk-offset scan + segment starts (1 block/n, 320 thr) =================
__global__ void __launch_bounds__(320)
hv_scan_kernel()
{
    const int n    = blockIdx.x;
    const int warp = threadIdx.x >> 5;   // class 0..9
    const int lane = threadIdx.x & 31;
    const unsigned FULL = 0xffffffffu;

    __shared__ int s_tot[10];

    int carry = 0;
    #pragma unroll
    for (int r = 0; r < (NCHUNK + 31) / 32; r++) {
        int j = r * 32 + lane;
        int v = (j < NCHUNK) ? g_chunkhist[n][j][warp] : 0;
        int incl = v;
        #pragma unroll
        for (int d = 1; d < 32; d <<= 1) {
            int t = __shfl_up_sync(FULL, incl, d);
            if (lane >= d) incl += t;
        }
        if (j < NCHUNK) g_chunkoff[n][j][warp] = carry + (incl - v);
        carry += __shfl_sync(FULL, incl, 31);
    }
    if (lane == 0) s_tot[warp] = carry;
    __syncthreads();

    if (threadIdx.x == 0) {
        int seg = 0;
        g_segStart[n][0] = 0;
        g_segStart[n][1] = 0;
        for (int k = 1; k < 10; k++) {
            seg += s_tot[k];
            g_segStart[n][k + 1] = seg;
        }
        for (int k = 0; k < 10; k++) g_counts[n][k] = (float)s_tot[k];
    }
}

// ================= K3: parallel stable scatter =================
__global__ void __launch_bounds__(PBLK)
hv_scatter_kernel()
{
    const int n   = blockIdx.y;
    const int idx = blockIdx.x * PBLK + threadIdx.x;
    const int lane = threadIdx.x & 31;
    const unsigned FULL = 0xffffffffu;

    __shared__ int s_seg[11];
    if (threadIdx.x < 11) s_seg[threadIdx.x] = g_segStart[n][threadIdx.x];
    __syncthreads();

    int l = (idx < P) ? g_plab[n][idx] : -1;
    int chunk = idx >> 5;

    #pragma unroll
    for (int k = 1; k < 10; k++) {
        unsigned m = __ballot_sync(FULL, l == k);
        if (l == k) {
            int pos = s_seg[k] + g_chunkoff[n][chunk][k] + __popc(m & ((1u << lane) - 1u));
            g_sxyuv[n][pos] = g_pxyuv[n][idx];
            g_sd[n][pos]    = g_pd[n][idx];
        }
    }
}

// ================= K4: voting (counts only) + fused argmax, 512 thr =================
__global__ void __launch_bounds__(VTHREADS)
hv_vote_kernel()
{
    const int n = blockIdx.z;
    const int k = blockIdx.y + 1;
    const int tid   = threadIdx.x;
    const int cl    = tid & (CBLK - 1);
    const int slice = tid >> 7;
    const int c     = blockIdx.x * CBLK + cl;

    __shared__ float4   sxy[VTILE];
    __shared__ int      s_pcnt[NSLICE][CBLK];
    __shared__ unsigned skey[CBLK];

    const int beg = g_segStart[n][k];
    const int end = g_segStart[n][k + 1];

    float fcx = 0.f, fcy = 0.f;
    const bool cv = (c < P);
    if (cv) {
        int iy = c / GX, ix = c - iy * GX;
        fcx = (float)(ix * SKIP);
        fcy = (float)(iy * SKIP);
    }

    int cnt = 0;

    for (int base = beg; base < end; base += VTILE) {
        int m = end - base;
        if (m > VTILE) m = VTILE;
        for (int j = tid; j < m; j += VTHREADS)
            sxy[j] = g_sxyuv[n][base + j];
        __syncthreads();
        for (int j = slice; j < m; j += NSLICE) {
            if (hv_inlier(fcx, fcy, sxy[j])) cnt++;
        }
        __syncthreads();
    }

    s_pcnt[slice][cl] = cnt;
    __syncthreads();

    if (slice == 0) {
        int tc = s_pcnt[0][cl] + s_pcnt[1][cl] + s_pcnt[2][cl] + s_pcnt[3][cl];
        skey[cl] = cv ? ((((unsigned)tc) << 13) | (unsigned)(8191 - c)) : 0u;
    }
    __syncthreads();

    for (int s = CBLK / 2; s > 0; s >>= 1) {
        if (tid < s) {
            unsigned o = skey[tid + s];
            if (o > skey[tid]) skey[tid] = o;
        }
        __syncthreads();
    }
    if (tid == 0)
        atomicMax(&g_bestkey[n][k], skey[0]);
}

// ================= K5: winner dsum + epilogue (1 block/n, warp per class) =================
__global__ void __launch_bounds__(320)
hv_final_kernel(const float* __restrict__ extents,
                const float* __restrict__ meta,
                float* __restrict__ out, int N)
{
    const int n    = blockIdx.x;
    const int warp = threadIdx.x >> 5;
    const int lane = threadIdx.x & 31;
    const unsigned FULL = 0xffffffffu;
    if (warp >= KD) return;

    const int k = warp + 1;
    unsigned bkey = g_bestkey[n][k];
    float votes = (float)(bkey >> 13);
    int   best  = 8191 - (int)(bkey & 8191u);
    int biy = best / GX, bix = best - biy * GX;
    float cx = (float)(bix * SKIP);
    float cy = (float)(biy * SKIP);

    const int beg = g_segStart[n][k];
    const int end = g_segStart[n][k + 1];

    float ds = 0.0f;
    for (int j = beg + lane; j < end; j += 32) {
        float4 t = g_sxyuv[n][j];
        if (hv_inlier(cx, cy, t)) ds += g_sd[n][j];
    }
    #pragma unroll
    for (int d = 16; d > 0; d >>= 1)
        ds += __shfl_down_sync(FULL, ds, d);

    if (lane == 0) {
        float davg = ds / fmaxf(votes, 1.0f);
        float cntk = g_counts[n][k];

        bool valid = (votes > 20.0f) && (votes > 0.1f * cntk)
                     && (cntk * (float)(SKIP * SKIP) > 500.0f);

        const float* mt = meta + (size_t)n * 9;
        float fx = mt[0], fy = mt[4], ppx = mt[2], ppy = mt[5];

        float e0 = extents[k * 3 + 0];
        float e1 = extents[k * 3 + 1];
        float e2 = extents[k * 3 + 2];
        float diam = sqrtf(e0 * e0 + e1 * e1 + e2 * e2) + EPSF;

        float hx = 0.5f * diam * fx / fmaxf(davg, EPSF);
        float hy = 0.5f * diam * fy / fmaxf(davg, EPSF);
        float score = valid ? votes : 0.0f;

        float* b = out + ((size_t)n * KD + (k - 1)) * 7;
        b[0] = (float)n;
        b[1] = (float)k;
        b[2] = cx - hx;
        b[3] = cy - hy;
        b[4] = cx + hx;
        b[5] = cy + hy;
        b[6] = score;

        float* ps = out + (size_t)N * KD * 7 + ((size_t)n * KD + (k - 1)) * 7;
        ps[0] = 1.0f; ps[1] = 0.0f; ps[2] = 0.0f; ps[3] = 0.0f;
        ps[4] = (cx - ppx) * davg / fx;
        ps[5] = (cy - ppy) * davg / fy;
        ps[6] = davg;

        out[(size_t)N * KD * 94 + (size_t)n * KD + (k - 1)] = (float)n;
    }
}

// ---------------- launch ----------------
extern "C" void kernel_launch(void* const* d_in, const int* in_sizes, int n_in,
                              void* d_out, int out_size)
{
    const int*   label   = (const int*)d_in[0];
    const float* vp      = (const float*)d_in[1];
    const float* extents = (const float*)d_in[2];
    const float* meta    = (const float*)d_in[4];
    float* out = (float*)d_out;

    int N = in_sizes[4] / 9;
    if (N < 1) N = 1;
    if (N > NMAX) N = NMAX;

    dim3 gp(PGRID, N);
    hv_prep_kernel<<<gp, PBLK>>>(label, vp, out, N);

    hv_scan_kernel<<<N, 320>>>();

    hv_scatter_kernel<<<gp, PBLK>>>();

    dim3 gv(VOTE_BX, KD, N);
    hv_vote_kernel<<<gv, VTHREADS>>>();

    hv_final_kernel<<<N, 320>>>(extents, meta, out, N);
}